// round 5
// baseline (speedup 1.0000x reference)
#include <cuda_runtime.h>
#include <cstdint>

// Instant-NGP fused forward, R5: tensor-core MLP (mma.sync m16n8k8 tf32).
// vs R4: (1) W2 read via __ldg (L1-hot) instead of smem staging -> 34.8KB smem;
// (2) launch_bounds(128,5) -> 20 warps/SM; (3) encode gathers batched in
// 4-level groups (16 loads in flight) to raise memory-level parallelism.

constexpr int NLV = 16;
constexpr int TSZ = 1 << 19;
constexpr unsigned PRIME_Y = 2654435761u;

constexpr int SA_STR = 33;   // feats: conflict-free encode stores
constexpr int SC_STR = 68;   // activations: conflict-free A-frag loads

__device__ __forceinline__ uint32_t f2tf(float f) {
    uint32_t u; asm("cvt.rna.tf32.f32 %0, %1;" : "=r"(u) : "f"(f)); return u;
}

__device__ __forceinline__ void mma8(float c[4], const uint32_t a[4], const uint32_t b[2]) {
    asm volatile("mma.sync.aligned.m16n8k8.row.col.f32.tf32.tf32.f32 "
                 "{%0,%1,%2,%3},{%4,%5,%6,%7},{%8,%9},{%0,%1,%2,%3};"
                 : "+f"(c[0]), "+f"(c[1]), "+f"(c[2]), "+f"(c[3])
                 : "r"(a[0]), "r"(a[1]), "r"(a[2]), "r"(a[3]), "r"(b[0]), "r"(b[1]));
}

__global__ __launch_bounds__(128, 5) void ngp_tc(
    const float* __restrict__ pos,      // [N,2]
    const float* __restrict__ table,    // [16, TSZ, 2]
    const float* __restrict__ W1,       // [32,64]
    const float* __restrict__ W2,       // [64,64]
    const float* __restrict__ W3,       // [64,3]
    float* __restrict__ out,            // [N,3]
    int n)
{
    __shared__ float sAct[128 * SC_STR];    // union: sA [128][33] then sC [128][68]

    const int t    = threadIdx.x;
    const int lane = t & 31;
    const int warp = t >> 5;
    const int m0   = warp * 32;
    const int g    = lane >> 2;             // groupID (0..7)
    const int q    = lane & 3;              // tid-in-group (0..3)
    const int base = blockIdx.x * 128;
    const int idx  = base + t;

    // ---- encode: feats -> sA[t][0..31] (tf32-rounded), 4 levels per batch ----
    {
        float2 p = (idx < n) ? ((const float2*)pos)[idx] : make_float2(0.f, 0.f);
#pragma unroll
        for (int lg = 0; lg < 4; lg++) {
            unsigned ix[4][4];
            float wgt[4][2];
            // phase 1: addresses + weights for 4 levels
#pragma unroll
            for (int l4 = 0; l4 < 4; l4++) {
                const int lvl = lg * 4 + l4;
                const int res = 16 << lvl;
                const float scale = (float)(res - 1);
                float px = p.x * scale + 0.5f;
                float py = p.y * scale + 0.5f;
                float fx = floorf(px), fy = floorf(py);
                wgt[l4][0] = px - fx;
                wgt[l4][1] = py - fy;
                unsigned cx = (unsigned)fx, cy = (unsigned)fy;
                if ((long long)res * res <= TSZ) {
                    unsigned i00 = cx + cy * (unsigned)res;
                    ix[l4][0] = i00;
                    ix[l4][1] = i00 + 1u;
                    ix[l4][2] = i00 + (unsigned)res;
                    ix[l4][3] = i00 + (unsigned)res + 1u;
                } else {
                    unsigned hy0 = cy * PRIME_Y;
                    unsigned hy1 = (cy + 1u) * PRIME_Y;
                    ix[l4][0] = (cx        ^ hy0) & (unsigned)(TSZ - 1);
                    ix[l4][1] = ((cx + 1u) ^ hy0) & (unsigned)(TSZ - 1);
                    ix[l4][2] = (cx        ^ hy1) & (unsigned)(TSZ - 1);
                    ix[l4][3] = ((cx + 1u) ^ hy1) & (unsigned)(TSZ - 1);
                }
            }
            // phase 2: issue all 16 gathers
            float2 v[4][4];
#pragma unroll
            for (int l4 = 0; l4 < 4; l4++) {
                const float2* tl = (const float2*)table + (size_t)(lg * 4 + l4) * TSZ;
#pragma unroll
                for (int c = 0; c < 4; c++) v[l4][c] = __ldg(tl + ix[l4][c]);
            }
            // phase 3: bilinear + store
#pragma unroll
            for (int l4 = 0; l4 < 4; l4++) {
                const int lvl = lg * 4 + l4;
                float wx = wgt[l4][0], wy = wgt[l4][1];
                float w00 = (1.f - wx) * (1.f - wy);
                float w10 = wx * (1.f - wy);
                float w01 = (1.f - wx) * wy;
                float w11 = wx * wy;
                float f0 = w00 * v[l4][0].x + w10 * v[l4][1].x + w01 * v[l4][2].x + w11 * v[l4][3].x;
                float f1 = w00 * v[l4][0].y + w10 * v[l4][1].y + w01 * v[l4][2].y + w11 * v[l4][3].y;
                sAct[t * SA_STR + 2 * lvl + 0] = __uint_as_float(f2tf(f0));
                sAct[t * SA_STR + 2 * lvl + 1] = __uint_as_float(f2tf(f1));
            }
        }
    }
    __syncwarp();

    // ---- GEMM1: C1[32x64] = A[32x32] @ W1[32x64]  (warp-local rows) ----
    float acc[2][8][4];
#pragma unroll
    for (int mt = 0; mt < 2; mt++)
#pragma unroll
        for (int nt = 0; nt < 8; nt++)
#pragma unroll
            for (int r = 0; r < 4; r++) acc[mt][nt][r] = 0.f;

#pragma unroll
    for (int k0 = 0; k0 < 32; k0 += 8) {
        uint32_t a[2][4];
#pragma unroll
        for (int mt = 0; mt < 2; mt++) {
            int r = m0 + mt * 16 + g;
            a[mt][0] = __float_as_uint(sAct[r * SA_STR + k0 + q]);
            a[mt][1] = __float_as_uint(sAct[(r + 8) * SA_STR + k0 + q]);
            a[mt][2] = __float_as_uint(sAct[r * SA_STR + k0 + q + 4]);
            a[mt][3] = __float_as_uint(sAct[(r + 8) * SA_STR + k0 + q + 4]);
        }
#pragma unroll
        for (int nt = 0; nt < 8; nt++) {
            uint32_t b[2];
            b[0] = f2tf(__ldg(&W1[(k0 + q)     * 64 + nt * 8 + g]));
            b[1] = f2tf(__ldg(&W1[(k0 + q + 4) * 64 + nt * 8 + g]));
            mma8(acc[0][nt], a[0], b);
            mma8(acc[1][nt], a[1], b);
        }
    }

    // all warps must finish reading sA before anyone overwrites it as sC
    __syncthreads();

    // ---- ReLU + store C1 (tf32-rounded) ----
#pragma unroll
    for (int mt = 0; mt < 2; mt++) {
        int r = m0 + mt * 16 + g;
#pragma unroll
        for (int nt = 0; nt < 8; nt++) {
            int c = nt * 8 + 2 * q;
            sAct[r * SC_STR + c]           = __uint_as_float(f2tf(fmaxf(acc[mt][nt][0], 0.f)));
            sAct[r * SC_STR + c + 1]       = __uint_as_float(f2tf(fmaxf(acc[mt][nt][1], 0.f)));
            sAct[(r + 8) * SC_STR + c]     = __uint_as_float(f2tf(fmaxf(acc[mt][nt][2], 0.f)));
            sAct[(r + 8) * SC_STR + c + 1] = __uint_as_float(f2tf(fmaxf(acc[mt][nt][3], 0.f)));
        }
    }
    __syncwarp();

    // ---- GEMM2: C2[32x64] = C1[32x64] @ W2[64x64] (W2 via __ldg, L1-hot) ----
    float acc2[2][8][4];
#pragma unroll
    for (int mt = 0; mt < 2; mt++)
#pragma unroll
        for (int nt = 0; nt < 8; nt++)
#pragma unroll
            for (int r = 0; r < 4; r++) acc2[mt][nt][r] = 0.f;

#pragma unroll
    for (int k0 = 0; k0 < 64; k0 += 8) {
        uint32_t a[2][4];
#pragma unroll
        for (int mt = 0; mt < 2; mt++) {
            int r = m0 + mt * 16 + g;
            a[mt][0] = __float_as_uint(sAct[r * SC_STR + k0 + q]);
            a[mt][1] = __float_as_uint(sAct[(r + 8) * SC_STR + k0 + q]);
            a[mt][2] = __float_as_uint(sAct[r * SC_STR + k0 + q + 4]);
            a[mt][3] = __float_as_uint(sAct[(r + 8) * SC_STR + k0 + q + 4]);
        }
#pragma unroll
        for (int nt = 0; nt < 8; nt++) {
            uint32_t b[2];
            b[0] = f2tf(__ldg(&W2[(k0 + q)     * 64 + nt * 8 + g]));
            b[1] = f2tf(__ldg(&W2[(k0 + q + 4) * 64 + nt * 8 + g]));
            mma8(acc2[0][nt], a[0], b);
            mma8(acc2[1][nt], a[1], b);
        }
    }

    // ---- epilogue: ReLU + layer3 (scalar fp32) + quad reduce ----
    float o[2][2][3];
#pragma unroll
    for (int mt = 0; mt < 2; mt++)
#pragma unroll
        for (int h = 0; h < 2; h++)
#pragma unroll
            for (int j = 0; j < 3; j++) o[mt][h][j] = 0.f;

#pragma unroll
    for (int nt = 0; nt < 8; nt++) {
        int c0 = nt * 8 + 2 * q;
        float w30[3], w31[3];
#pragma unroll
        for (int j = 0; j < 3; j++) {
            w30[j] = __ldg(&W3[c0 * 3 + j]);
            w31[j] = __ldg(&W3[(c0 + 1) * 3 + j]);
        }
#pragma unroll
        for (int mt = 0; mt < 2; mt++) {
            float v0 = fmaxf(acc2[mt][nt][0], 0.f);
            float v1 = fmaxf(acc2[mt][nt][1], 0.f);
            float v2 = fmaxf(acc2[mt][nt][2], 0.f);
            float v3 = fmaxf(acc2[mt][nt][3], 0.f);
#pragma unroll
            for (int j = 0; j < 3; j++) {
                o[mt][0][j] += v0 * w30[j] + v1 * w31[j];
                o[mt][1][j] += v2 * w30[j] + v3 * w31[j];
            }
        }
    }

#pragma unroll
    for (int mt = 0; mt < 2; mt++)
#pragma unroll
        for (int h = 0; h < 2; h++)
#pragma unroll
            for (int j = 0; j < 3; j++) {
                float v = o[mt][h][j];
                v += __shfl_xor_sync(0xffffffffu, v, 1);
                v += __shfl_xor_sync(0xffffffffu, v, 2);
                o[mt][h][j] = v;
            }

    if (q < 3) {
        int j = q;
#pragma unroll
        for (int mt = 0; mt < 2; mt++)
#pragma unroll
            for (int h = 0; h < 2; h++) {
                int row = base + m0 + mt * 16 + g + h * 8;
                if (row < n) out[row * 3 + j] = o[mt][h][j];
            }
    }
}

extern "C" void kernel_launch(void* const* d_in, const int* in_sizes, int n_in,
                              void* d_out, int out_size) {
    const float* pos   = (const float*)d_in[0];
    const float* table = (const float*)d_in[1];
    const float* W1    = (const float*)d_in[2];
    const float* W2    = (const float*)d_in[3];
    const float* W3    = (const float*)d_in[4];
    float* out = (float*)d_out;
    int n = in_sizes[0] / 2;
    int blocks = (n + 127) / 128;
    ngp_tc<<<blocks, 128>>>(pos, table, W1, W2, W3, out, n);
}

// round 6
// speedup vs baseline: 1.0550x; 1.0550x over previous
#include <cuda_runtime.h>
#include <cstdint>

// Instant-NGP fused forward, R6: tensor-core MLP (mma.sync m16n8k8 tf32).
// vs R4 (best, 1704us): (1) per-warp smem blocks, sA aliases inside own sC
// block -> no __syncthreads, warps fully decoupled; (2) GEMM2 accumulator
// split into two n-halves (peak regs 64->32 there) so 5 CTAs/SM fit without
// spill; (3) sA stride 36 -> conflict-free GEMM1 a-frag LDS.

constexpr int NLV = 16;
constexpr int TSZ = 1 << 19;
constexpr unsigned PRIME_Y = 2654435761u;

constexpr int SA_STR = 36;   // feats: conflict-free a-frag loads (bank=4*row+q)
constexpr int SC_STR = 68;   // activations: conflict-free a-frag loads
constexpr int WBLK   = 32 * SC_STR;   // 2176 floats per warp block

__device__ __forceinline__ uint32_t f2tf(float f) {
    uint32_t u; asm("cvt.rna.tf32.f32 %0, %1;" : "=r"(u) : "f"(f)); return u;
}

__device__ __forceinline__ void mma8(float c[4], const uint32_t a[4], const uint32_t b[2]) {
    asm volatile("mma.sync.aligned.m16n8k8.row.col.f32.tf32.tf32.f32 "
                 "{%0,%1,%2,%3},{%4,%5,%6,%7},{%8,%9},{%0,%1,%2,%3};"
                 : "+f"(c[0]), "+f"(c[1]), "+f"(c[2]), "+f"(c[3])
                 : "r"(a[0]), "r"(a[1]), "r"(a[2]), "r"(a[3]), "r"(b[0]), "r"(b[1]));
}

__global__ __launch_bounds__(128, 5) void ngp_tc(
    const float* __restrict__ pos,      // [N,2]
    const float* __restrict__ table,    // [16, TSZ, 2]
    const float* __restrict__ W1,       // [32,64]
    const float* __restrict__ W2,       // [64,64]
    const float* __restrict__ W3,       // [64,3]
    float* __restrict__ out,            // [N,3]
    int n)
{
    __shared__ float sm[4 * WBLK];      // 34816 B; per-warp 8704 B block

    const int t    = threadIdx.x;
    const int lane = t & 31;
    const int warp = t >> 5;
    const int g    = lane >> 2;             // groupID (0..7)
    const int q    = lane & 3;              // tid-in-group (0..3)
    const int base = blockIdx.x * 128;
    const int idx  = base + t;

    float* sW = sm + warp * WBLK;           // this warp's block
    // sA view: row lr (0..31) at sW + lr*SA_STR  (fits in first 1152 floats)
    // sC view: row lr (0..31) at sW + lr*SC_STR

    // ---- encode: feats -> sA[lane][0..31] (tf32-rounded) ----
    {
        float2 p = (idx < n) ? ((const float2*)pos)[idx] : make_float2(0.f, 0.f);
#pragma unroll
        for (int lvl = 0; lvl < NLV; lvl++) {
            const int res = 16 << lvl;
            const float scale = (float)(res - 1);
            float px = p.x * scale + 0.5f;
            float py = p.y * scale + 0.5f;
            float fx = floorf(px), fy = floorf(py);
            float wx = px - fx,    wy = py - fy;
            unsigned cx = (unsigned)fx, cy = (unsigned)fy;

            unsigned i00, i10, i01, i11;
            if ((long long)res * res <= TSZ) {
                i00 = cx + cy * (unsigned)res;
                i10 = i00 + 1u;
                i01 = i00 + (unsigned)res;
                i11 = i01 + 1u;
            } else {
                unsigned hy0 = cy * PRIME_Y;
                unsigned hy1 = (cy + 1u) * PRIME_Y;
                i00 = (cx        ^ hy0) & (unsigned)(TSZ - 1);
                i10 = ((cx + 1u) ^ hy0) & (unsigned)(TSZ - 1);
                i01 = (cx        ^ hy1) & (unsigned)(TSZ - 1);
                i11 = ((cx + 1u) ^ hy1) & (unsigned)(TSZ - 1);
            }

            const float2* tl = (const float2*)table + (size_t)lvl * TSZ;
            float2 v00 = __ldg(tl + i00);
            float2 v10 = __ldg(tl + i10);
            float2 v01 = __ldg(tl + i01);
            float2 v11 = __ldg(tl + i11);

            float w00 = (1.f - wx) * (1.f - wy);
            float w10 = wx * (1.f - wy);
            float w01 = (1.f - wx) * wy;
            float w11 = wx * wy;

            float f0 = w00 * v00.x + w10 * v10.x + w01 * v01.x + w11 * v11.x;
            float f1 = w00 * v00.y + w10 * v10.y + w01 * v01.y + w11 * v11.y;

            sW[lane * SA_STR + 2 * lvl + 0] = __uint_as_float(f2tf(f0));
            sW[lane * SA_STR + 2 * lvl + 1] = __uint_as_float(f2tf(f1));
        }
    }
    __syncwarp();

    // ---- GEMM1: C1[32x64] = A[32x32] @ W1[32x64] ----
    float acc[2][8][4];
#pragma unroll
    for (int mt = 0; mt < 2; mt++)
#pragma unroll
        for (int nt = 0; nt < 8; nt++)
#pragma unroll
            for (int r = 0; r < 4; r++) acc[mt][nt][r] = 0.f;

#pragma unroll
    for (int k0 = 0; k0 < 32; k0 += 8) {
        uint32_t a[2][4];
#pragma unroll
        for (int mt = 0; mt < 2; mt++) {
            int lr = mt * 16 + g;
            a[mt][0] = __float_as_uint(sW[lr * SA_STR + k0 + q]);
            a[mt][1] = __float_as_uint(sW[(lr + 8) * SA_STR + k0 + q]);
            a[mt][2] = __float_as_uint(sW[lr * SA_STR + k0 + q + 4]);
            a[mt][3] = __float_as_uint(sW[(lr + 8) * SA_STR + k0 + q + 4]);
        }
#pragma unroll
        for (int nt = 0; nt < 8; nt++) {
            uint32_t b[2];
            b[0] = f2tf(__ldg(&W1[(k0 + q)     * 64 + nt * 8 + g]));
            b[1] = f2tf(__ldg(&W1[(k0 + q + 4) * 64 + nt * 8 + g]));
            mma8(acc[0][nt], a[0], b);
            mma8(acc[1][nt], a[1], b);
        }
    }
    __syncwarp();   // sA reads done (warp-local) before overwrite as sC

    // ---- ReLU + store C1 (tf32-rounded) into sC ----
#pragma unroll
    for (int mt = 0; mt < 2; mt++) {
        int lr = mt * 16 + g;
#pragma unroll
        for (int nt = 0; nt < 8; nt++) {
            int c = nt * 8 + 2 * q;
            sW[lr * SC_STR + c]           = __uint_as_float(f2tf(fmaxf(acc[mt][nt][0], 0.f)));
            sW[lr * SC_STR + c + 1]       = __uint_as_float(f2tf(fmaxf(acc[mt][nt][1], 0.f)));
            sW[(lr + 8) * SC_STR + c]     = __uint_as_float(f2tf(fmaxf(acc[mt][nt][2], 0.f)));
            sW[(lr + 8) * SC_STR + c + 1] = __uint_as_float(f2tf(fmaxf(acc[mt][nt][3], 0.f)));
        }
    }
    __syncwarp();

    // ---- GEMM2 (n split in two halves of 32) + layer3 fold; h2 never stored ----
    float o[2][2][3];
#pragma unroll
    for (int mt = 0; mt < 2; mt++)
#pragma unroll
        for (int h = 0; h < 2; h++)
#pragma unroll
            for (int j = 0; j < 3; j++) o[mt][h][j] = 0.f;

#pragma unroll
    for (int nh = 0; nh < 2; nh++) {
        float acc2[2][4][4];
#pragma unroll
        for (int mt = 0; mt < 2; mt++)
#pragma unroll
            for (int nt = 0; nt < 4; nt++)
#pragma unroll
                for (int r = 0; r < 4; r++) acc2[mt][nt][r] = 0.f;

#pragma unroll
        for (int k0 = 0; k0 < 64; k0 += 8) {
            uint32_t a[2][4];
#pragma unroll
            for (int mt = 0; mt < 2; mt++) {
                int lr = mt * 16 + g;
                a[mt][0] = __float_as_uint(sW[lr * SC_STR + k0 + q]);
                a[mt][1] = __float_as_uint(sW[(lr + 8) * SC_STR + k0 + q]);
                a[mt][2] = __float_as_uint(sW[lr * SC_STR + k0 + q + 4]);
                a[mt][3] = __float_as_uint(sW[(lr + 8) * SC_STR + k0 + q + 4]);
            }
#pragma unroll
            for (int nt = 0; nt < 4; nt++) {
                int ng = nh * 4 + nt;
                uint32_t b[2];
                b[0] = f2tf(__ldg(&W2[(k0 + q)     * 64 + ng * 8 + g]));
                b[1] = f2tf(__ldg(&W2[(k0 + q + 4) * 64 + ng * 8 + g]));
                mma8(acc2[0][nt], a[0], b);
                mma8(acc2[1][nt], a[1], b);
            }
        }

        // fold this n-half into layer-3 partials
#pragma unroll
        for (int nt = 0; nt < 4; nt++) {
            int c0 = (nh * 4 + nt) * 8 + 2 * q;
            float w30[3], w31[3];
#pragma unroll
            for (int j = 0; j < 3; j++) {
                w30[j] = __ldg(&W3[c0 * 3 + j]);
                w31[j] = __ldg(&W3[(c0 + 1) * 3 + j]);
            }
#pragma unroll
            for (int mt = 0; mt < 2; mt++) {
                float v0 = fmaxf(acc2[mt][nt][0], 0.f);
                float v1 = fmaxf(acc2[mt][nt][1], 0.f);
                float v2 = fmaxf(acc2[mt][nt][2], 0.f);
                float v3 = fmaxf(acc2[mt][nt][3], 0.f);
#pragma unroll
                for (int j = 0; j < 3; j++) {
                    o[mt][0][j] += v0 * w30[j] + v1 * w31[j];
                    o[mt][1][j] += v2 * w30[j] + v3 * w31[j];
                }
            }
        }
    }

    // reduce across the 4 lanes of each quad (they partition the 64 columns)
#pragma unroll
    for (int mt = 0; mt < 2; mt++)
#pragma unroll
        for (int h = 0; h < 2; h++)
#pragma unroll
            for (int j = 0; j < 3; j++) {
                float v = o[mt][h][j];
                v += __shfl_xor_sync(0xffffffffu, v, 1);
                v += __shfl_xor_sync(0xffffffffu, v, 2);
                o[mt][h][j] = v;
            }

    if (q < 3) {
        int j = q;
#pragma unroll
        for (int mt = 0; mt < 2; mt++)
#pragma unroll
            for (int h = 0; h < 2; h++) {
                int row = base + warp * 32 + mt * 16 + g + h * 8;
                if (row < n) out[row * 3 + j] = o[mt][h][j];
            }
    }
}

extern "C" void kernel_launch(void* const* d_in, const int* in_sizes, int n_in,
                              void* d_out, int out_size) {
    const float* pos   = (const float*)d_in[0];
    const float* table = (const float*)d_in[1];
    const float* W1    = (const float*)d_in[2];
    const float* W2    = (const float*)d_in[3];
    const float* W3    = (const float*)d_in[4];
    float* out = (float*)d_out;
    int n = in_sizes[0] / 2;
    int blocks = (n + 127) / 128;
    ngp_tc<<<blocks, 128>>>(pos, table, W1, W2, W3, out, n);
}

// round 7
// speedup vs baseline: 1.2147x; 1.1513x over previous
#include <cuda_runtime.h>
#include <cstdint>

// Instant-NGP fused forward, R7: tensor-core MLP (mma.sync m16n8k8 tf32).
// Spill-free envelope of R4 (4 CTAs, 128 regs) + per-warp smem decoupling (no
// late __syncthreads), W2 pre-converted in smem, and 2-level gather batching
// (8 loads in flight) in the encode phase.

constexpr int NLV = 16;
constexpr int TSZ = 1 << 19;
constexpr unsigned PRIME_Y = 2654435761u;

constexpr int SA_STR = 36;            // feats: bank = 4g+q, conflict-free a-frags
constexpr int SC_STR = 68;            // activations: bank = 4g+q, conflict-free
constexpr int SW2_STR = 68;
constexpr int WBLK   = 32 * SC_STR;   // 2176 floats per warp block
constexpr int SMEM_FLOATS = 4 * WBLK + 64 * SW2_STR;     // 13056
constexpr int SMEM_BYTES  = SMEM_FLOATS * 4;             // 52224

__device__ __forceinline__ uint32_t f2tf(float f) {
    uint32_t u; asm("cvt.rna.tf32.f32 %0, %1;" : "=r"(u) : "f"(f)); return u;
}

__device__ __forceinline__ void mma8(float c[4], const uint32_t a[4], const uint32_t b[2]) {
    asm volatile("mma.sync.aligned.m16n8k8.row.col.f32.tf32.tf32.f32 "
                 "{%0,%1,%2,%3},{%4,%5,%6,%7},{%8,%9},{%0,%1,%2,%3};"
                 : "+f"(c[0]), "+f"(c[1]), "+f"(c[2]), "+f"(c[3])
                 : "r"(a[0]), "r"(a[1]), "r"(a[2]), "r"(a[3]), "r"(b[0]), "r"(b[1]));
}

__global__ __launch_bounds__(128, 4) void ngp_tc(
    const float* __restrict__ pos,      // [N,2]
    const float* __restrict__ table,    // [16, TSZ, 2]
    const float* __restrict__ W1,       // [32,64]
    const float* __restrict__ W2,       // [64,64]
    const float* __restrict__ W3,       // [64,3]
    float* __restrict__ out,            // [N,3]
    int n)
{
    extern __shared__ float sm[];
    float* sW2 = sm + 4 * WBLK;             // [64][68], tf32-rounded, CTA-shared

    const int t    = threadIdx.x;
    const int lane = t & 31;
    const int warp = t >> 5;
    const int g    = lane >> 2;             // groupID (0..7)
    const int q    = lane & 3;              // tid-in-group (0..3)
    const int base = blockIdx.x * 128;
    const int idx  = base + t;

    float* sW = sm + warp * WBLK;           // this warp's activation block
    // sA view: row lr at sW + lr*SA_STR (first 1152 floats); sC view: lr*SC_STR

    // ---- stage W2 (tf32-rounded) into CTA-shared smem, then the ONLY CTA sync ----
    for (int i = t; i < 64 * 64; i += 128) {
        int k = i >> 6, c = i & 63;
        sW2[k * SW2_STR + c] = __uint_as_float(f2tf(W2[i]));
    }
    __syncthreads();

    // ---- encode: feats -> sA[lane][0..31], 2 levels batched (8 loads in flight) ----
    {
        float2 p = (idx < n) ? ((const float2*)pos)[idx] : make_float2(0.f, 0.f);
#pragma unroll
        for (int lp = 0; lp < 8; lp++) {
            unsigned ix[2][4];
            float wgt[2][2];
#pragma unroll
            for (int l2 = 0; l2 < 2; l2++) {
                const int lvl = lp * 2 + l2;
                const int res = 16 << lvl;
                const float scale = (float)(res - 1);
                float px = p.x * scale + 0.5f;
                float py = p.y * scale + 0.5f;
                float fx = floorf(px), fy = floorf(py);
                wgt[l2][0] = px - fx;
                wgt[l2][1] = py - fy;
                unsigned cx = (unsigned)fx, cy = (unsigned)fy;
                if ((long long)res * res <= TSZ) {
                    unsigned i00 = cx + cy * (unsigned)res;
                    ix[l2][0] = i00;
                    ix[l2][1] = i00 + 1u;
                    ix[l2][2] = i00 + (unsigned)res;
                    ix[l2][3] = i00 + (unsigned)res + 1u;
                } else {
                    unsigned hy0 = cy * PRIME_Y;
                    unsigned hy1 = (cy + 1u) * PRIME_Y;
                    ix[l2][0] = (cx        ^ hy0) & (unsigned)(TSZ - 1);
                    ix[l2][1] = ((cx + 1u) ^ hy0) & (unsigned)(TSZ - 1);
                    ix[l2][2] = (cx        ^ hy1) & (unsigned)(TSZ - 1);
                    ix[l2][3] = ((cx + 1u) ^ hy1) & (unsigned)(TSZ - 1);
                }
            }
            float2 v[2][4];
#pragma unroll
            for (int l2 = 0; l2 < 2; l2++) {
                const float2* tl = (const float2*)table + (size_t)(lp * 2 + l2) * TSZ;
#pragma unroll
                for (int c = 0; c < 4; c++) v[l2][c] = __ldg(tl + ix[l2][c]);
            }
#pragma unroll
            for (int l2 = 0; l2 < 2; l2++) {
                const int lvl = lp * 2 + l2;
                float wx = wgt[l2][0], wy = wgt[l2][1];
                float w00 = (1.f - wx) * (1.f - wy);
                float w10 = wx * (1.f - wy);
                float w01 = (1.f - wx) * wy;
                float w11 = wx * wy;
                float f0 = w00 * v[l2][0].x + w10 * v[l2][1].x + w01 * v[l2][2].x + w11 * v[l2][3].x;
                float f1 = w00 * v[l2][0].y + w10 * v[l2][1].y + w01 * v[l2][2].y + w11 * v[l2][3].y;
                sW[lane * SA_STR + 2 * lvl + 0] = __uint_as_float(f2tf(f0));
                sW[lane * SA_STR + 2 * lvl + 1] = __uint_as_float(f2tf(f1));
            }
        }
    }
    __syncwarp();

    // ---- GEMM1: C1[32x64] = A[32x32] @ W1[32x64] (warp-local) ----
    float acc[2][8][4];
#pragma unroll
    for (int mt = 0; mt < 2; mt++)
#pragma unroll
        for (int nt = 0; nt < 8; nt++)
#pragma unroll
            for (int r = 0; r < 4; r++) acc[mt][nt][r] = 0.f;

#pragma unroll
    for (int k0 = 0; k0 < 32; k0 += 8) {
        uint32_t a[2][4];
#pragma unroll
        for (int mt = 0; mt < 2; mt++) {
            int lr = mt * 16 + g;
            a[mt][0] = __float_as_uint(sW[lr * SA_STR + k0 + q]);
            a[mt][1] = __float_as_uint(sW[(lr + 8) * SA_STR + k0 + q]);
            a[mt][2] = __float_as_uint(sW[lr * SA_STR + k0 + q + 4]);
            a[mt][3] = __float_as_uint(sW[(lr + 8) * SA_STR + k0 + q + 4]);
        }
#pragma unroll
        for (int nt = 0; nt < 8; nt++) {
            uint32_t b[2];
            b[0] = f2tf(__ldg(&W1[(k0 + q)     * 64 + nt * 8 + g]));
            b[1] = f2tf(__ldg(&W1[(k0 + q + 4) * 64 + nt * 8 + g]));
            mma8(acc[0][nt], a[0], b);
            mma8(acc[1][nt], a[1], b);
        }
    }
    __syncwarp();   // warp-local: all sA reads done before overwrite as sC

    // ---- ReLU + store C1 (tf32-rounded) into sC ----
#pragma unroll
    for (int mt = 0; mt < 2; mt++) {
        int lr = mt * 16 + g;
#pragma unroll
        for (int nt = 0; nt < 8; nt++) {
            int c = nt * 8 + 2 * q;
            sW[lr * SC_STR + c]           = __uint_as_float(f2tf(fmaxf(acc[mt][nt][0], 0.f)));
            sW[lr * SC_STR + c + 1]       = __uint_as_float(f2tf(fmaxf(acc[mt][nt][1], 0.f)));
            sW[(lr + 8) * SC_STR + c]     = __uint_as_float(f2tf(fmaxf(acc[mt][nt][2], 0.f)));
            sW[(lr + 8) * SC_STR + c + 1] = __uint_as_float(f2tf(fmaxf(acc[mt][nt][3], 0.f)));
        }
    }
    __syncwarp();

    // ---- GEMM2: C2[32x64] = C1[32x64] @ W2[64x64] (b-frags from smem) ----
    float acc2[2][8][4];
#pragma unroll
    for (int mt = 0; mt < 2; mt++)
#pragma unroll
        for (int nt = 0; nt < 8; nt++)
#pragma unroll
            for (int r = 0; r < 4; r++) acc2[mt][nt][r] = 0.f;

#pragma unroll
    for (int k0 = 0; k0 < 64; k0 += 8) {
        uint32_t a[2][4];
#pragma unroll
        for (int mt = 0; mt < 2; mt++) {
            int lr = mt * 16 + g;
            a[mt][0] = __float_as_uint(sW[lr * SC_STR + k0 + q]);
            a[mt][1] = __float_as_uint(sW[(lr + 8) * SC_STR + k0 + q]);
            a[mt][2] = __float_as_uint(sW[lr * SC_STR + k0 + q + 4]);
            a[mt][3] = __float_as_uint(sW[(lr + 8) * SC_STR + k0 + q + 4]);
        }
#pragma unroll
        for (int nt = 0; nt < 8; nt++) {
            uint32_t b[2];
            b[0] = __float_as_uint(sW2[(k0 + q)     * SW2_STR + nt * 8 + g]);
            b[1] = __float_as_uint(sW2[(k0 + q + 4) * SW2_STR + nt * 8 + g]);
            mma8(acc2[0][nt], a[0], b);
            mma8(acc2[1][nt], a[1], b);
        }
    }

    // ---- epilogue: ReLU + layer3 (scalar fp32) + quad reduce ----
    float o[2][2][3];
#pragma unroll
    for (int mt = 0; mt < 2; mt++)
#pragma unroll
        for (int h = 0; h < 2; h++)
#pragma unroll
            for (int j = 0; j < 3; j++) o[mt][h][j] = 0.f;

#pragma unroll
    for (int nt = 0; nt < 8; nt++) {
        int c0 = nt * 8 + 2 * q;
        float w30[3], w31[3];
#pragma unroll
        for (int j = 0; j < 3; j++) {
            w30[j] = __ldg(&W3[c0 * 3 + j]);
            w31[j] = __ldg(&W3[(c0 + 1) * 3 + j]);
        }
#pragma unroll
        for (int mt = 0; mt < 2; mt++) {
            float v0 = fmaxf(acc2[mt][nt][0], 0.f);
            float v1 = fmaxf(acc2[mt][nt][1], 0.f);
            float v2 = fmaxf(acc2[mt][nt][2], 0.f);
            float v3 = fmaxf(acc2[mt][nt][3], 0.f);
#pragma unroll
            for (int j = 0; j < 3; j++) {
                o[mt][0][j] += v0 * w30[j] + v1 * w31[j];
                o[mt][1][j] += v2 * w30[j] + v3 * w31[j];
            }
        }
    }

#pragma unroll
    for (int mt = 0; mt < 2; mt++)
#pragma unroll
        for (int h = 0; h < 2; h++)
#pragma unroll
            for (int j = 0; j < 3; j++) {
                float v = o[mt][h][j];
                v += __shfl_xor_sync(0xffffffffu, v, 1);
                v += __shfl_xor_sync(0xffffffffu, v, 2);
                o[mt][h][j] = v;
            }

    if (q < 3) {
        int j = q;
#pragma unroll
        for (int mt = 0; mt < 2; mt++)
#pragma unroll
            for (int h = 0; h < 2; h++) {
                int row = base + warp * 32 + mt * 16 + g + h * 8;
                if (row < n) out[row * 3 + j] = o[mt][h][j];
            }
    }
}

extern "C" void kernel_launch(void* const* d_in, const int* in_sizes, int n_in,
                              void* d_out, int out_size) {
    const float* pos   = (const float*)d_in[0];
    const float* table = (const float*)d_in[1];
    const float* W1    = (const float*)d_in[2];
    const float* W2    = (const float*)d_in[3];
    const float* W3    = (const float*)d_in[4];
    float* out = (float*)d_out;
    int n = in_sizes[0] / 2;
    int blocks = (n + 127) / 128;

    static bool attr_set = false;
    if (!attr_set) {
        cudaFuncSetAttribute(ngp_tc, cudaFuncAttributeMaxDynamicSharedMemorySize,
                             SMEM_BYTES);
        attr_set = true;
    }
    ngp_tc<<<blocks, 128, SMEM_BYTES>>>(pos, table, W1, W2, W3, out, n);
}